// round 5
// baseline (speedup 1.0000x reference)
#include <cuda_runtime.h>
#include <math.h>

// Problem constants
#define BB    32
#define LL    65536          // T*K
#define CC    6
#define POSB  1024           // positions per block
#define NCH   (LL / POSB)    // 64 chunks per batch
#define TPB   512            // 16 warps; thread owns 2 positions x 6 channels
#define GRID  (BB * NCH)     // 2048 blocks

// -ln(a), a = 1 - theta*dt = 0.99999 ; a^{-t} = exp(t*LPc)
#define LPc 1.0000050000333335e-05f
// sqrt(2*theta*dt) = sqrt(2e-5)
#define SQc 4.4721359549995794e-03f

// Scratch (device globals; init_kernel resets g_agg every replay)
__device__ unsigned long long g_agg[BB * NCH * CC];  // packed (f32<<32 | flag)
__device__ float g_temp[LL];
__device__ float g_ainv[LL];   // a^{-t}
__device__ float g_apos[LL];   // a^{+t}

__device__ __forceinline__ float ch_std0(int c)  { return (c < 3) ? 0.2f   : 0.015f; }
__device__ __forceinline__ float ch_noise(int c) { return (c < 3) ? 0.1f   : 0.01f;  }
__device__ __forceinline__ float ch_tcoef(int c) { return (c < 3) ? 0.001f : 0.01f;  }

// ---------------------------------------------------------------------------
// Init: temperature + power tables, and reset lookback flags.
// ---------------------------------------------------------------------------
__global__ void init_kernel() {
    int t = blockIdx.x * blockDim.x + threadIdx.x;
    if (t < LL) {
        float tt = (float)t / (float)(LL - 1);
        g_temp[t] = 20.0f + 5.0f * sinf(6.283185307179586f * tt) + 2.0f * tt;
        float x = (float)t * LPc;
        g_ainv[t] = expf(x);
        g_apos[t] = expf(-x);
    }
    if (t < BB * NCH * CC) g_agg[t] = 0ULL;
}

// ---------------------------------------------------------------------------
// 12 walk floats feeding 2 positions (shifted: w_t uses walk[t-1]; w_0 = 0).
// ---------------------------------------------------------------------------
__device__ __forceinline__ void load_walk12(const float* __restrict__ walk,
                                            int b, int p0, float wv[12]) {
    if (p0 == 0) {
        const float* w2 = walk + (size_t)b * (LL - 1) * CC;
        #pragma unroll
        for (int i = 0; i < 6; ++i) wv[i] = 0.0f;
        #pragma unroll
        for (int i = 0; i < 3; ++i) {
            float2 v = *(const float2*)(w2 + 2 * i);
            wv[6 + 2 * i] = v.x; wv[7 + 2 * i] = v.y;
        }
    } else {
        const float* wp = walk + (size_t)b * (LL - 1) * CC + (size_t)(p0 - 1) * CC;
        #pragma unroll
        for (int i = 0; i < 6; ++i) {
            float2 v = *(const float2*)(wp + 2 * i);
            wv[2 * i] = v.x; wv[2 * i + 1] = v.y;
        }
    }
}

// ---------------------------------------------------------------------------
// Fused single-pass kernel: local scan + deterministic aggregate lookback +
// bias reconstruction + epilogue. One read of each input, one write of out.
// ---------------------------------------------------------------------------
__global__ __launch_bounds__(TPB, 2) void fused_kernel(
    const float* __restrict__ imu,
    const float* __restrict__ eps0,
    const float* __restrict__ walk,
    const float* __restrict__ meas,
    float* __restrict__ out)
{
    __shared__ float wsum[16][CC];
    __shared__ float wexc[16][CC];
    __shared__ float bcast[CC];

    const int bx = blockIdx.x;
    const int b = bx >> 6, k = bx & (NCH - 1);
    const int tid = threadIdx.x;
    const int w = tid >> 5, l = tid & 31;
    const int tstart = k * POSB;
    const int p0 = tstart + tid * 2;

    float wv[12];
    load_walk12(walk, b, p0, wv);

    const float2 aiv = *(const float2*)&g_ainv[p0];   // a^{-p0}, a^{-p0-1}
    const float2 apv = *(const float2*)&g_apos[p0];   // a^{+p0}, a^{+p0+1}

    float w0[CC], w1[CC], t6[CC];
    #pragma unroll
    for (int c = 0; c < CC; ++c) {
        float ds = ch_std0(c) * SQc;
        w0[c] = wv[c] * ds * aiv.x;
        w1[c] = wv[6 + c] * ds * aiv.y;
        t6[c] = w0[c] + w1[c];
    }

    // warp-inclusive scan per channel (6 parallel chains)
    float incl[CC];
    #pragma unroll
    for (int c = 0; c < CC; ++c) incl[c] = t6[c];
    #pragma unroll
    for (int d = 1; d < 32; d <<= 1)
        #pragma unroll
        for (int c = 0; c < CC; ++c) {
            float o = __shfl_up_sync(0xffffffffu, incl[c], d);
            if (l >= d) incl[c] += o;
        }
    if (l == 31)
        #pragma unroll
        for (int c = 0; c < CC; ++c) wsum[w][c] = incl[c];
    __syncthreads();

    // warp 0: second-level scan, publish aggregate, lookback over predecessors
    if (w == 0) {
        float v[CC], inc2[CC];
        #pragma unroll
        for (int c = 0; c < CC; ++c) {
            v[c] = (l < 16) ? wsum[l][c] : 0.0f;
            inc2[c] = v[c];
        }
        #pragma unroll
        for (int d = 1; d < 16; d <<= 1)
            #pragma unroll
            for (int c = 0; c < CC; ++c) {
                float o = __shfl_up_sync(0xffffffffu, inc2[c], d);
                if (l >= d) inc2[c] += o;
            }
        if (l < 16)
            #pragma unroll
            for (int c = 0; c < CC; ++c) wexc[l][c] = inc2[c] - v[c];

        // block totals, broadcast to all lanes
        float tot[CC];
        #pragma unroll
        for (int c = 0; c < CC; ++c) tot[c] = __shfl_sync(0xffffffffu, inc2[c], 15);

        // publish packed (value, flag) — 8B atomic store, no fence needed
        #pragma unroll
        for (int c = 0; c < CC; ++c)
            if (l == c) {
                unsigned long long p =
                    ((unsigned long long)__float_as_uint(tot[c]) << 32) | 1ULL;
                *((volatile unsigned long long*)&g_agg[bx * CC + c]) = p;
            }

        // deterministic lookback: sum ALL predecessor aggregates (fixed order)
        float exc[CC];
        #pragma unroll
        for (int c = 0; c < CC; ++c) exc[c] = 0.0f;
        for (int win = 0; win * 32 < k; ++win) {
            const int pk = win * 32 + l;
            const bool valid = pk < k;
            float pv[CC];
            if (valid) {
                const int pbase = (b * NCH + pk) * CC;
                #pragma unroll
                for (int c = 0; c < CC; ++c) {
                    unsigned long long u;
                    while (!((u = *((volatile unsigned long long*)&g_agg[pbase + c])) & 1ULL))
                        __nanosleep(32);
                    pv[c] = __uint_as_float((unsigned)(u >> 32));
                }
            } else {
                #pragma unroll
                for (int c = 0; c < CC; ++c) pv[c] = 0.0f;
            }
            #pragma unroll
            for (int d = 16; d >= 1; d >>= 1)
                #pragma unroll
                for (int c = 0; c < CC; ++c)
                    pv[c] += __shfl_down_sync(0xffffffffu, pv[c], d);
            if (l == 0)
                #pragma unroll
                for (int c = 0; c < CC; ++c) exc[c] += pv[c];
        }
        if (l == 0)
            #pragma unroll
            for (int c = 0; c < CC; ++c) bcast[c] = exc[c];
    }
    __syncthreads();

    // bias for both positions, in registers
    float bias0[CC], bias1[CC];
    #pragma unroll
    for (int c = 0; c < CC; ++c) {
        float carry = eps0[b * CC + c] * ch_std0(c) + bcast[c];
        float base = carry + wexc[w][c] + (incl[c] - t6[c]);
        bias0[c] = (base + w0[c]) * apv.x;
        bias1[c] = (base + t6[c]) * apv.y;
    }

    // fused epilogue: 12 contiguous floats, 3x float4 in/out
    const size_t gb = ((size_t)b * LL + tstart) * CC + (size_t)tid * 12;
    const float2 tm = *(const float2*)&g_temp[p0];

    float bias[12], tadd[12], ns[12];
    #pragma unroll
    for (int c = 0; c < CC; ++c) {
        bias[c] = bias0[c];          bias[6 + c] = bias1[c];
        tadd[c] = tm.x * ch_tcoef(c); tadd[6 + c] = tm.y * ch_tcoef(c);
        ns[c] = ch_noise(c);          ns[6 + c] = ch_noise(c);
    }
    #pragma unroll
    for (int q = 0; q < 3; ++q) {
        float4 vi = *(const float4*)(imu + gb + q * 4);
        float4 vm = *(const float4*)(meas + gb + q * 4);
        float4 o4;
        o4.x = vi.x + bias[q * 4 + 0] + vm.x * ns[q * 4 + 0] + tadd[q * 4 + 0];
        o4.y = vi.y + bias[q * 4 + 1] + vm.y * ns[q * 4 + 1] + tadd[q * 4 + 1];
        o4.z = vi.z + bias[q * 4 + 2] + vm.z * ns[q * 4 + 2] + tadd[q * 4 + 2];
        o4.w = vi.w + bias[q * 4 + 3] + vm.w * ns[q * 4 + 3] + tadd[q * 4 + 3];
        *(float4*)(out + gb + q * 4) = o4;
    }
}

// ---------------------------------------------------------------------------
extern "C" void kernel_launch(void* const* d_in, const int* in_sizes, int n_in,
                              void* d_out, int out_size) {
    const float* imu  = (const float*)d_in[0];   // [32, 4096, 16, 6]
    const float* eps0 = (const float*)d_in[1];   // [32, 6]
    const float* walk = (const float*)d_in[2];   // [32, 65535, 6]
    const float* meas = (const float*)d_in[3];   // [32, 65536, 6]
    float* out = (float*)d_out;

    init_kernel<<<(LL + 1023) / 1024, 1024>>>();
    fused_kernel<<<GRID, TPB>>>(imu, eps0, walk, meas, out);
}